// round 16
// baseline (speedup 1.0000x reference)
#include <cuda_runtime.h>
#include <cuda_fp16.h>
#include <cstdint>
#include <math.h>

#define T_SEQ    2048
#define B_BATCH  2
#define DM       1024
#define NHEAD    16
#define HDIM     64
#define ROWS     (B_BATCH * T_SEQ)      // 4096
#define QKV_COLS (3 * DM)               // 3072

// Scratch (allocation-guard compliant: device globals) — all fp16
__device__ __half g_attn16[(size_t)ROWS * DM];          // 8 MB
__device__ __half g_x16[(size_t)ROWS * DM];             // 8 MB
__device__ __half g_WqkvT16[(size_t)QKV_COLS * DM];     // 6 MB [N][K]
__device__ __half g_WoutT16[(size_t)DM * DM];           // 2 MB [N][K]
__device__ float  g_rope_tab[(size_t)T_SEQ * 32 * 2];   // 512 KB (sin,cos)
// Packed per-head fp16 tensors [b][h][t][64]
__device__ __half g_qpk[(size_t)ROWS * DM];             // 8 MB (q * 1/8)
__device__ __half g_kpk[(size_t)ROWS * DM];             // 8 MB
__device__ __half g_vpk[(size_t)ROWS * DM];             // 8 MB

__device__ __forceinline__ uint32_t smem_u32(const void* p) {
    uint32_t a;
    asm("{ .reg .u64 t; cvta.to.shared.u64 t, %1; cvt.u32.u64 %0, t; }"
        : "=r"(a) : "l"(p));
    return a;
}
__device__ __forceinline__ void cp16(uint32_t dst, const void* src) {
    asm volatile("cp.async.cg.shared.global [%0], [%1], 16;"
                 :: "r"(dst), "l"(src));
}
#define CP_COMMIT() asm volatile("cp.async.commit_group;" ::: "memory")
#define CP_WAIT2()  asm volatile("cp.async.wait_group 2;" ::: "memory")
#define CP_WAIT1()  asm volatile("cp.async.wait_group 1;" ::: "memory")
#define CP_WAIT0()  asm volatile("cp.async.wait_group 0;" ::: "memory")

__device__ __forceinline__ void mma_f16(
    float* c, uint32_t a0, uint32_t a1, uint32_t a2, uint32_t a3,
    uint32_t b0, uint32_t b1)
{
    asm volatile(
        "mma.sync.aligned.m16n8k16.row.col.f32.f16.f16.f32 "
        "{%0,%1,%2,%3}, {%4,%5,%6,%7}, {%8,%9}, {%0,%1,%2,%3};"
        : "+f"(c[0]), "+f"(c[1]), "+f"(c[2]), "+f"(c[3])
        : "r"(a0), "r"(a1), "r"(a2), "r"(a3), "r"(b0), "r"(b1));
}
__device__ __forceinline__ void ldsm_x4(
    uint32_t& r0, uint32_t& r1, uint32_t& r2, uint32_t& r3, uint32_t addr)
{
    asm volatile("ldmatrix.sync.aligned.m8n8.x4.shared.b16 {%0,%1,%2,%3}, [%4];"
                 : "=r"(r0), "=r"(r1), "=r"(r2), "=r"(r3) : "r"(addr));
}
__device__ __forceinline__ void ldsm_x4_trans(
    uint32_t& r0, uint32_t& r1, uint32_t& r2, uint32_t& r3, uint32_t addr)
{
    asm volatile("ldmatrix.sync.aligned.m8n8.x4.trans.shared.b16 {%0,%1,%2,%3}, [%4];"
                 : "=r"(r0), "=r"(r1), "=r"(r2), "=r"(r3) : "r"(addr));
}

// ===========================================================================
// Fused prologue: one launch covering
//   [0, NB_CONV)                     : x -> fp16 copy
//   [NB_CONV, +NB_TQKV)              : Wqkv transpose -> fp16 [N][K]
//   [.., +NB_TOUT)                   : Wout transpose -> fp16 [N][K]
//   [.., +NB_ROPE)                   : RoPE sin/cos table
// Identical per-element numerics to the previous 4 kernels.
// ===========================================================================
#define NB_CONV 4096
#define NB_TQKV 3072   // (QKV_COLS/32) x (DM/32) = 96 x 32
#define NB_TOUT 1024   // 32 x 32
#define NB_ROPE 256
#define NB_TOTAL (NB_CONV + NB_TQKV + NB_TOUT + NB_ROPE)

__device__ __forceinline__ void transpose_block(
    const float* __restrict__ src, __half* __restrict__ dst,
    int R, int C, int bx, int by, int tid)
{
    __shared__ float tile[32][33];
    const int c0 = bx * 32, r0 = by * 32;
    const int x = tid & 31, y = tid >> 5;   // 32 x 8
#pragma unroll
    for (int i = 0; i < 32; i += 8)
        tile[y + i][x] = src[(size_t)(r0 + y + i) * C + c0 + x];
    __syncthreads();
#pragma unroll
    for (int i = 0; i < 32; i += 8)
        dst[(size_t)(c0 + y + i) * R + r0 + x] = __float2half_rn(tile[x][y + i]);
}

__global__ void prologue_kernel(const float* __restrict__ x,
                                const float* __restrict__ Wqkv,
                                const float* __restrict__ Wout)
{
    const int bid = blockIdx.x;
    const int tid = threadIdx.x;

    if (bid < NB_CONV) {
        const size_t i = (size_t)bid * 256 + tid;
        float4 v = *(const float4*)(x + 4 * i);
        *(__half2*)&g_x16[4 * i]     = __floats2half2_rn(v.x, v.y);
        *(__half2*)&g_x16[4 * i + 2] = __floats2half2_rn(v.z, v.w);
    } else if (bid < NB_CONV + NB_TQKV) {
        const int id = bid - NB_CONV;
        transpose_block(Wqkv, g_WqkvT16, DM, QKV_COLS, id % 96, id / 96, tid);
    } else if (bid < NB_CONV + NB_TQKV + NB_TOUT) {
        const int id = bid - NB_CONV - NB_TQKV;
        transpose_block(Wout, g_WoutT16, DM, DM, id % 32, id / 32, tid);
    } else {
        const int idx = (bid - NB_CONV - NB_TQKV - NB_TOUT) * 256 + tid;
        const int i = idx & 31;
        const int t = idx >> 5;
        double ang = (double)t * pow(10000.0, -(double)i / 32.0);
        g_rope_tab[2 * idx + 0] = (float)sin(ang);
        g_rope_tab[2 * idx + 1] = (float)cos(ang);
    }
}

// ===========================================================================
// fp16 GEMM mainloop: 128x128 tile, BK=32 halves, 4-stage cp.async,
// all-x4 ldmatrix frags, m16n8k16 fp16 mma w/ fp32 accum. Stride 40 halves.
// ===========================================================================
#define SSTH 40
#define NSTG 4
#define STG_HALVES (128 * SSTH)
#define GEMM_SMEM (NSTG * 2 * STG_HALVES * 2)   // 81920 B

__device__ __forceinline__ void gemm_mainloop_f16(
    const __half* __restrict__ A, const __half* __restrict__ Bt,
    int K, int bm, int bn, float acc[4][4][4], __half* sm)
{
    const int tid  = threadIdx.x;
    const int lane = tid & 31;
    const int wid  = tid >> 5;
    const int wm   = (wid >> 2) * 64;
    const int wn   = (wid & 3) * 32;

    __half* As = sm;
    __half* Bs = sm + NSTG * STG_HALVES;
    const uint32_t as0 = smem_u32(As);
    const uint32_t bs0 = smem_u32(Bs);
    const int r0 = tid >> 1;               // row 0..127
    const int c0 = (tid & 1) * 16;         // half offset

    const uint32_t a_lane = (uint32_t)((((lane >> 3) & 1) * 8 + (lane & 7)) * (SSTH * 2)
                                       + (lane >> 4) * 16);
    const uint32_t b_lane4 = (uint32_t)((lane & 7) * (SSTH * 2)
                                        + ((lane >> 3) & 1) * 16
                                        + (lane >> 4) * 8 * (SSTH * 2));

    auto issue = [&](int ch) {
        const int s  = ch & (NSTG - 1);
        const int k0 = ch << 5;            // halves
        const uint32_t ao = as0 + (uint32_t)(s * STG_HALVES + r0 * SSTH + c0) * 2;
        const uint32_t bo = bs0 + (uint32_t)(s * STG_HALVES + r0 * SSTH + c0) * 2;
        cp16(ao,      A  + (size_t)(bm + r0) * K + k0 + c0);
        cp16(ao + 16, A  + (size_t)(bm + r0) * K + k0 + c0 + 8);
        cp16(bo,      Bt + (size_t)(bn + r0) * K + k0 + c0);
        cp16(bo + 16, Bt + (size_t)(bn + r0) * K + k0 + c0 + 8);
        CP_COMMIT();
    };

    const int niter = K >> 5;              // BK = 32 halves
    issue(0); issue(1); issue(2);

    for (int it = 0; it < niter; it++) {
        CP_WAIT2();
        __syncthreads();
        if (it + 3 < niter) issue(it + 3);

        const uint32_t abase = as0 + (uint32_t)((it & (NSTG - 1)) * STG_HALVES) * 2;
        const uint32_t bbase = bs0 + (uint32_t)((it & (NSTG - 1)) * STG_HALVES) * 2;

#pragma unroll
        for (int ks = 0; ks < 2; ks++) {   // two k16 steps, +32B each
            uint32_t afr[4][4], bfr[4][2];
#pragma unroll
            for (int mt = 0; mt < 4; mt++) {
                const uint32_t ad = abase
                    + (uint32_t)((wm + mt * 16) * (SSTH * 2)) + ks * 32 + a_lane;
                ldsm_x4(afr[mt][0], afr[mt][1], afr[mt][2], afr[mt][3], ad);
            }
#pragma unroll
            for (int nt = 0; nt < 4; nt += 2) {
                const uint32_t bd = bbase
                    + (uint32_t)((wn + nt * 8) * (SSTH * 2)) + ks * 32 + b_lane4;
                ldsm_x4(bfr[nt][0], bfr[nt][1], bfr[nt + 1][0], bfr[nt + 1][1], bd);
            }
#pragma unroll
            for (int mt = 0; mt < 4; mt++)
#pragma unroll
                for (int nt = 0; nt < 4; nt++)
                    mma_f16(acc[mt][nt], afr[mt][0], afr[mt][1], afr[mt][2],
                            afr[mt][3], bfr[nt][0], bfr[nt][1]);
        }
    }
}

// ---------------------------------------------------------------------------
// QKV GEMM (fp16) with fused RoPE + per-head pack epilogue (fp16 outputs).
// ---------------------------------------------------------------------------
__global__ __launch_bounds__(256, 2) void gemm_qkv_fused(
    const __half* __restrict__ A, const __half* __restrict__ Bt, int K)
{
    extern __shared__ __half smh[];
    const int tid  = threadIdx.x;
    const int lane = tid & 31;
    const int wid  = tid >> 5;
    const int wm   = (wid >> 2) * 64;
    const int wn   = (wid & 3) * 32;
    const int bm   = blockIdx.y * 128;
    const int bn   = blockIdx.x * 128;
    const int gid  = lane >> 2;
    const int tig  = lane & 3;

    float acc[4][4][4];
#pragma unroll
    for (int i = 0; i < 4; i++)
#pragma unroll
        for (int j = 0; j < 4; j++)
#pragma unroll
            for (int q = 0; q < 4; q++) acc[i][j][q] = 0.0f;

    gemm_mainloop_f16(A, Bt, K, bm, bn, acc, smh);

#pragma unroll
    for (int mt = 0; mt < 4; mt++) {
        const int rb = bm + wm + mt * 16 + gid;
#pragma unroll
        for (int nt = 0; nt < 4; nt++) {
            const int c  = bn + wn + nt * 8 + 2 * tig;
            const int region = c >> 10;
            const int cc = c & 1023;
            const int h  = cc >> 6;
            const int d  = cc & 63;
            const int i2 = d >> 1;
#pragma unroll
            for (int half = 0; half < 2; half++) {
                const int r = rb + half * 8;
                const int t = r & (T_SEQ - 1);
                const int b = r >> 11;
                const float a0 = acc[mt][nt][2 * half + 0];
                const float a1 = acc[mt][nt][2 * half + 1];
                const size_t dst =
                    ((size_t)(b * NHEAD + h) * T_SEQ + t) * HDIM + d;
                if (region == 2) {
                    *(__half2*)&g_vpk[dst] = __floats2half2_rn(a0, a1);
                } else {
                    const float sn = g_rope_tab[2 * (t * 32 + i2) + 0];
                    const float cs = g_rope_tab[2 * (t * 32 + i2) + 1];
                    float o0 = a0 * cs - a1 * sn;
                    float o1 = a1 * cs + a0 * sn;
                    if (region == 0) {
                        *(__half2*)&g_qpk[dst] =
                            __floats2half2_rn(o0 * 0.125f, o1 * 0.125f);
                    } else {
                        *(__half2*)&g_kpk[dst] = __floats2half2_rn(o0, o1);
                    }
                }
            }
        }
    }
}

// ---------------------------------------------------------------------------
// Plain fp16 GEMM, fp32 output (output projection)
// ---------------------------------------------------------------------------
__global__ __launch_bounds__(256, 2) void gemm_f16(
    const __half* __restrict__ A, const __half* __restrict__ Bt,
    float* __restrict__ C, int N, int K)
{
    extern __shared__ __half smh[];
    const int tid  = threadIdx.x;
    const int lane = tid & 31;
    const int wid  = tid >> 5;
    const int wm   = (wid >> 2) * 64;
    const int wn   = (wid & 3) * 32;
    const int bm   = blockIdx.y * 128;
    const int bn   = blockIdx.x * 128;
    const int gid  = lane >> 2;
    const int tig  = lane & 3;

    float acc[4][4][4];
#pragma unroll
    for (int i = 0; i < 4; i++)
#pragma unroll
        for (int j = 0; j < 4; j++)
#pragma unroll
            for (int q = 0; q < 4; q++) acc[i][j][q] = 0.0f;

    gemm_mainloop_f16(A, Bt, K, bm, bn, acc, smh);

#pragma unroll
    for (int mt = 0; mt < 4; mt++) {
        const int rb = bm + wm + mt * 16;
#pragma unroll
        for (int nt = 0; nt < 4; nt++) {
            const int cb = bn + wn + nt * 8 + 2 * tig;
            float2 lo = {acc[mt][nt][0], acc[mt][nt][1]};
            float2 hi = {acc[mt][nt][2], acc[mt][nt][3]};
            *(float2*)(C + (size_t)(rb + gid)     * N + cb) = lo;
            *(float2*)(C + (size_t)(rb + gid + 8) * N + cb) = hi;
        }
    }
}

// ===========================================================================
// fp16 tensor-core causal flash attention (128 q-rows, 8 warps).
// __launch_bounds__(256, 2) guarantees 2 CTAs/SM (live state ~115 regs < 128).
// Strides 72 halves. All fragments via ldmatrix.x4 (nt-pairs merged).
// ===========================================================================
#define SKP 72
#define SV  72
#define FA_SMEM ((2 * 64 * SKP + 2 * 64 * SV + 128 * SKP) * 2)   // 55296 B

__global__ __launch_bounds__(256, 2) void flash_attn_tc()
{
    extern __shared__ __half smh[];
    __half* Ksm = smh;                       // [2][key][d]  stride 72
    __half* Vsm = Ksm + 2 * 64 * SKP;        // [2][key][d]  stride 72
    __half* Psm = Vsm + 2 * 64 * SV;         // [m][key]     stride 72

    const int tid  = threadIdx.x;
    const int lane = tid & 31;
    const int wid  = tid >> 5;
    const int gid  = lane >> 2;
    const int tig  = lane & 3;
    const int qi = (int)(gridDim.x - 1 - blockIdx.x);
    const int h = blockIdx.y, b = blockIdx.z;
    const int qbase = qi * 128;
    const int bh = b * NHEAD + h;
    const int wrow = 16 * wid;

    const uint32_t ksm0 = smem_u32(Ksm);
    const uint32_t vsm0 = smem_u32(Vsm);
    const uint32_t psm0 = smem_u32(Psm);
    const __half* kbase_p = g_kpk + (size_t)bh * T_SEQ * HDIM;
    const __half* vbase_p = g_vpk + (size_t)bh * T_SEQ * HDIM;

    const uint32_t k_lane4 = (uint32_t)((lane & 7) * (SKP * 2)
                                        + ((lane >> 3) & 1) * 16
                                        + (lane >> 4) * 8 * (SKP * 2));
    const uint32_t p_lane = (uint32_t)((((lane >> 3) & 1) * 8 + (lane & 7)) * (SKP * 2)
                                       + (lane >> 4) * 16);
    const uint32_t v_lane4 = (uint32_t)((lane & 15) * (SV * 2)
                                        + (lane >> 4) * 16);

    auto issue_kv = [&](int kt, int st) {
        const int n = tid >> 2;                 // key 0..63
        const int q = (tid & 3) * 16;           // half offset (32B chunks)
        const size_t go = (size_t)(kt * 64 + n) * HDIM + q;
        const uint32_t ko = (uint32_t)(st * 64 * SKP + n * SKP + q) * 2;
        const uint32_t vo = (uint32_t)(st * 64 * SV  + n * SV  + q) * 2;
        cp16(ko + ksm0,      kbase_p + go);
        cp16(ko + ksm0 + 16, kbase_p + go + 8);
        cp16(vo + vsm0,      vbase_p + go);
        cp16(vo + vsm0 + 16, vbase_p + go + 8);
    };

    // stage Q (fp16, pre-scaled) into Psm: 256 threads cover 128 rows
    {
        int m = tid >> 1;
        int d0 = (tid & 1) * 32;
        const __half* src = g_qpk + ((size_t)bh * T_SEQ + qbase + m) * HDIM + d0;
#pragma unroll
        for (int j = 0; j < 4; j++) {
            uint4 v = *(const uint4*)(src + 8 * j);
            *(uint4*)&Psm[m * SKP + d0 + 8 * j] = v;
        }
    }

    const int nkt = qbase / 64 + 2;
    issue_kv(0, 0);
    CP_COMMIT();
    __syncthreads();

    // hoist Q fragments (4 k16-steps over d=64)
    uint32_t qf[4][4];
#pragma unroll
    for (int kp = 0; kp < 4; kp++) {
        const uint32_t qa = psm0 + (uint32_t)(wrow * (SKP * 2)) + kp * 32 + p_lane;
        ldsm_x4(qf[kp][0], qf[kp][1], qf[kp][2], qf[kp][3], qa);
    }

    float Oacc[8][4];
#pragma unroll
    for (int nt = 0; nt < 8; nt++)
#pragma unroll
        for (int q = 0; q < 4; q++) Oacc[nt][q] = 0.0f;
    float mrow0 = -1e30f, mrow1 = -1e30f, lrow0 = 0.0f, lrow1 = 0.0f;

    for (int kt = 0; kt < nkt; kt++) {
        const int st = kt & 1;
        const int kb = kt * 64;
        const bool more = (kt + 1) < nkt;
        if (more) { issue_kv(kt + 1, st ^ 1); CP_COMMIT(); }
        if (more) { CP_WAIT1(); } else { CP_WAIT0(); }
        __syncthreads();

        const uint32_t kst = ksm0 + (uint32_t)(st * 64 * SKP * 2);
        const uint32_t vst = vsm0 + (uint32_t)(st * 64 * SV * 2);

        // ---- S = Q @ K^T  (K frags x4, nt-pairs) ----
        float sacc[8][4];
#pragma unroll
        for (int nt = 0; nt < 8; nt++)
#pragma unroll
            for (int q = 0; q < 4; q++) sacc[nt][q] = 0.0f;

#pragma unroll
        for (int kp = 0; kp < 4; kp++) {
#pragma unroll
            for (int nt = 0; nt < 8; nt += 2) {
                uint32_t b0, b1, b2, b3;
                const uint32_t ka = kst
                    + (uint32_t)(nt * 8 * (SKP * 2)) + kp * 32 + k_lane4;
                ldsm_x4(b0, b1, b2, b3, ka);
                mma_f16(sacc[nt],     qf[kp][0], qf[kp][1], qf[kp][2], qf[kp][3],
                        b0, b1);
                mma_f16(sacc[nt + 1], qf[kp][0], qf[kp][1], qf[kp][2], qf[kp][3],
                        b2, b3);
            }
        }

        // ---- causal mask (last two tiles only) ----
        const int r0g = qbase + wrow + gid;
        if (kb + 63 > qbase) {
#pragma unroll
            for (int nt = 0; nt < 8; nt++) {
                int col = kb + nt * 8 + 2 * tig;
                if (col     > r0g)     sacc[nt][0] = -1e30f;
                if (col + 1 > r0g)     sacc[nt][1] = -1e30f;
                if (col     > r0g + 8) sacc[nt][2] = -1e30f;
                if (col + 1 > r0g + 8) sacc[nt][3] = -1e30f;
            }
        }

        // ---- online softmax ----
        float mx0 = -1e30f, mx1 = -1e30f;
#pragma unroll
        for (int nt = 0; nt < 8; nt++) {
            mx0 = fmaxf(mx0, fmaxf(sacc[nt][0], sacc[nt][1]));
            mx1 = fmaxf(mx1, fmaxf(sacc[nt][2], sacc[nt][3]));
        }
        mx0 = fmaxf(mx0, __shfl_xor_sync(0xffffffffu, mx0, 1));
        mx0 = fmaxf(mx0, __shfl_xor_sync(0xffffffffu, mx0, 2));
        mx1 = fmaxf(mx1, __shfl_xor_sync(0xffffffffu, mx1, 1));
        mx1 = fmaxf(mx1, __shfl_xor_sync(0xffffffffu, mx1, 2));
        const float nm0 = fmaxf(mrow0, mx0);
        const float nm1 = fmaxf(mrow1, mx1);

        float sum0 = 0.0f, sum1 = 0.0f;
#pragma unroll
        for (int nt = 0; nt < 8; nt++) {
            float p00 = __expf(sacc[nt][0] - nm0);
            float p01 = __expf(sacc[nt][1] - nm0);
            float p10 = __expf(sacc[nt][2] - nm1);
            float p11 = __expf(sacc[nt][3] - nm1);
            sum0 += p00 + p01;
            sum1 += p10 + p11;
            *(__half2*)&Psm[(wrow + gid)     * SKP + nt * 8 + 2 * tig] =
                __floats2half2_rn(p00, p01);
            *(__half2*)&Psm[(wrow + gid + 8) * SKP + nt * 8 + 2 * tig] =
                __floats2half2_rn(p10, p11);
        }
        sum0 += __shfl_xor_sync(0xffffffffu, sum0, 1);
        sum0 += __shfl_xor_sync(0xffffffffu, sum0, 2);
        sum1 += __shfl_xor_sync(0xffffffffu, sum1, 1);
        sum1 += __shfl_xor_sync(0xffffffffu, sum1, 2);

        const float a0 = __expf(mrow0 - nm0);
        const float a1 = __expf(mrow1 - nm1);
        lrow0 = lrow0 * a0 + sum0;
        lrow1 = lrow1 * a1 + sum1;
        mrow0 = nm0; mrow1 = nm1;
#pragma unroll
        for (int nt = 0; nt < 8; nt++) {
            Oacc[nt][0] *= a0; Oacc[nt][1] *= a0;
            Oacc[nt][2] *= a1; Oacc[nt][3] *= a1;
        }
        __syncwarp();

        // ---- O += P @ V  (V frags x4.trans, nt-pairs) ----
#pragma unroll
        for (int kk = 0; kk < 4; kk++) {
            uint32_t a0f, a1f, a2f, a3f;
            const uint32_t pa = psm0
                + (uint32_t)(wrow * (SKP * 2)) + kk * 32 + p_lane;
            ldsm_x4(a0f, a1f, a2f, a3f, pa);
#pragma unroll
            for (int nt = 0; nt < 8; nt += 2) {
                uint32_t b0, b1, b2, b3;
                const uint32_t va = vst
                    + (uint32_t)(kk * 16 * (SV * 2)) + nt * 16 + v_lane4;
                ldsm_x4_trans(b0, b1, b2, b3, va);
                mma_f16(Oacc[nt],     a0f, a1f, a2f, a3f, b0, b1);
                mma_f16(Oacc[nt + 1], a0f, a1f, a2f, a3f, b2, b3);
            }
        }
        __syncthreads();
    }

    const float i0 = 1.0f / lrow0;
    const float i1 = 1.0f / lrow1;
    const int r0g = qbase + wrow + gid;
#pragma unroll
    for (int nt = 0; nt < 8; nt++) {
        const int c = h * HDIM + nt * 8 + 2 * tig;
        *(__half2*)&g_attn16[((size_t)b * T_SEQ + r0g)     * DM + c] =
            __floats2half2_rn(Oacc[nt][0] * i0, Oacc[nt][1] * i0);
        *(__half2*)&g_attn16[((size_t)b * T_SEQ + r0g + 8) * DM + c] =
            __floats2half2_rn(Oacc[nt][2] * i1, Oacc[nt][3] * i1);
    }
}

// ===========================================================================
extern "C" void kernel_launch(void* const* d_in, const int* in_sizes, int n_in,
                              void* d_out, int out_size)
{
    const float* x    = (const float*)d_in[0];
    const float* Wqkv = (const float*)d_in[1];
    const float* Wout = (const float*)d_in[2];
    float* out = (float*)d_out;

    __half *attn16 = nullptr, *wqkvT = nullptr, *woutT = nullptr, *x16 = nullptr;
    cudaGetSymbolAddress((void**)&attn16, g_attn16);
    cudaGetSymbolAddress((void**)&wqkvT,  g_WqkvT16);
    cudaGetSymbolAddress((void**)&woutT,  g_WoutT16);
    cudaGetSymbolAddress((void**)&x16,    g_x16);

    cudaFuncSetAttribute(gemm_qkv_fused,
                         cudaFuncAttributeMaxDynamicSharedMemorySize, GEMM_SMEM);
    cudaFuncSetAttribute(gemm_f16,
                         cudaFuncAttributeMaxDynamicSharedMemorySize, GEMM_SMEM);
    cudaFuncSetAttribute(flash_attn_tc,
                         cudaFuncAttributeMaxDynamicSharedMemorySize, FA_SMEM);

    // 0) Fused prologue (x convert + both transposes + RoPE table)
    prologue_kernel<<<NB_TOTAL, 256>>>(x, Wqkv, Wout);

    // 1) QKV projection (fp16 mma) + fused RoPE + per-head pack
    gemm_qkv_fused<<<dim3(QKV_COLS / 128, ROWS / 128), 256, GEMM_SMEM>>>(
        x16, wqkvT, DM);

    // 2) Causal flash attention (fp16 mma, 128-row CTAs, 2 CTAs/SM)
    flash_attn_tc<<<dim3(T_SEQ / 128, NHEAD, B_BATCH), 256, FA_SMEM>>>();

    // 3) Output projection (fp16 mma, fp32 out)
    gemm_f16<<<dim3(DM / 128, ROWS / 128), 256, GEMM_SMEM>>>(
        attn16, woutT, out, DM, DM);
}

// round 17
// speedup vs baseline: 1.0249x; 1.0249x over previous
#include <cuda_runtime.h>
#include <cuda_fp16.h>
#include <cstdint>
#include <math.h>

#define T_SEQ    2048
#define B_BATCH  2
#define DM       1024
#define NHEAD    16
#define HDIM     64
#define ROWS     (B_BATCH * T_SEQ)      // 4096
#define QKV_COLS (3 * DM)               // 3072

// Scratch (allocation-guard compliant: device globals) — all fp16
__device__ __half g_attn16[(size_t)ROWS * DM];          // 8 MB
__device__ __half g_x16[(size_t)ROWS * DM];             // 8 MB
__device__ __half g_WqkvT16[(size_t)QKV_COLS * DM];     // 6 MB [N][K]
__device__ __half g_WoutT16[(size_t)DM * DM];           // 2 MB [N][K]
__device__ float  g_rope_tab[(size_t)T_SEQ * 32 * 2];   // 512 KB (sin,cos)
// Packed per-head fp16 tensors [b][h][t][64]
__device__ __half g_qpk[(size_t)ROWS * DM];             // 8 MB (q * 1/8)
__device__ __half g_kpk[(size_t)ROWS * DM];             // 8 MB
__device__ __half g_vpk[(size_t)ROWS * DM];             // 8 MB

__device__ __forceinline__ uint32_t smem_u32(const void* p) {
    uint32_t a;
    asm("{ .reg .u64 t; cvta.to.shared.u64 t, %1; cvt.u32.u64 %0, t; }"
        : "=r"(a) : "l"(p));
    return a;
}
__device__ __forceinline__ void cp16(uint32_t dst, const void* src) {
    asm volatile("cp.async.cg.shared.global [%0], [%1], 16;"
                 :: "r"(dst), "l"(src));
}
#define CP_COMMIT() asm volatile("cp.async.commit_group;" ::: "memory")
#define CP_WAIT2()  asm volatile("cp.async.wait_group 2;" ::: "memory")
#define CP_WAIT1()  asm volatile("cp.async.wait_group 1;" ::: "memory")
#define CP_WAIT0()  asm volatile("cp.async.wait_group 0;" ::: "memory")

__device__ __forceinline__ void mma_f16(
    float* c, uint32_t a0, uint32_t a1, uint32_t a2, uint32_t a3,
    uint32_t b0, uint32_t b1)
{
    asm volatile(
        "mma.sync.aligned.m16n8k16.row.col.f32.f16.f16.f32 "
        "{%0,%1,%2,%3}, {%4,%5,%6,%7}, {%8,%9}, {%0,%1,%2,%3};"
        : "+f"(c[0]), "+f"(c[1]), "+f"(c[2]), "+f"(c[3])
        : "r"(a0), "r"(a1), "r"(a2), "r"(a3), "r"(b0), "r"(b1));
}
__device__ __forceinline__ void ldsm_x4(
    uint32_t& r0, uint32_t& r1, uint32_t& r2, uint32_t& r3, uint32_t addr)
{
    asm volatile("ldmatrix.sync.aligned.m8n8.x4.shared.b16 {%0,%1,%2,%3}, [%4];"
                 : "=r"(r0), "=r"(r1), "=r"(r2), "=r"(r3) : "r"(addr));
}
__device__ __forceinline__ void ldsm_x4_trans(
    uint32_t& r0, uint32_t& r1, uint32_t& r2, uint32_t& r3, uint32_t addr)
{
    asm volatile("ldmatrix.sync.aligned.m8n8.x4.trans.shared.b16 {%0,%1,%2,%3}, [%4];"
                 : "=r"(r0), "=r"(r1), "=r"(r2), "=r"(r3) : "r"(addr));
}

// ===========================================================================
// Fused prologue (R16-style): x convert + both transposes + RoPE table
// ===========================================================================
#define NB_CONV 4096
#define NB_TQKV 3072   // (QKV_COLS/32) x (DM/32) = 96 x 32
#define NB_TOUT 1024   // 32 x 32
#define NB_ROPE 256
#define NB_TOTAL (NB_CONV + NB_TQKV + NB_TOUT + NB_ROPE)

__device__ __forceinline__ void transpose_block(
    const float* __restrict__ src, __half* __restrict__ dst,
    int R, int C, int bx, int by, int tid)
{
    __shared__ float tile[32][33];
    const int c0 = bx * 32, r0 = by * 32;
    const int x = tid & 31, y = tid >> 5;   // 32 x 8
#pragma unroll
    for (int i = 0; i < 32; i += 8)
        tile[y + i][x] = src[(size_t)(r0 + y + i) * C + c0 + x];
    __syncthreads();
#pragma unroll
    for (int i = 0; i < 32; i += 8)
        dst[(size_t)(c0 + y + i) * R + r0 + x] = __float2half_rn(tile[x][y + i]);
}

__global__ void prologue_kernel(const float* __restrict__ x,
                                const float* __restrict__ Wqkv,
                                const float* __restrict__ Wout)
{
    const int bid = blockIdx.x;
    const int tid = threadIdx.x;

    if (bid < NB_CONV) {
        const size_t i = (size_t)bid * 256 + tid;
        float4 v = *(const float4*)(x + 4 * i);
        *(__half2*)&g_x16[4 * i]     = __floats2half2_rn(v.x, v.y);
        *(__half2*)&g_x16[4 * i + 2] = __floats2half2_rn(v.z, v.w);
    } else if (bid < NB_CONV + NB_TQKV) {
        const int id = bid - NB_CONV;
        transpose_block(Wqkv, g_WqkvT16, DM, QKV_COLS, id % 96, id / 96, tid);
    } else if (bid < NB_CONV + NB_TQKV + NB_TOUT) {
        const int id = bid - NB_CONV - NB_TQKV;
        transpose_block(Wout, g_WoutT16, DM, DM, id % 32, id / 32, tid);
    } else {
        const int idx = (bid - NB_CONV - NB_TQKV - NB_TOUT) * 256 + tid;
        const int i = idx & 31;
        const int t = idx >> 5;
        double ang = (double)t * pow(10000.0, -(double)i / 32.0);
        g_rope_tab[2 * idx + 0] = (float)sin(ang);
        g_rope_tab[2 * idx + 1] = (float)cos(ang);
    }
}

// ===========================================================================
// fp16 GEMM mainloop: 128x128 tile, BK=32 halves, 4-stage cp.async,
// all-x4 ldmatrix frags, m16n8k16 fp16 mma w/ fp32 accum. Stride 40 halves.
// ===========================================================================
#define SSTH 40
#define NSTG 4
#define STG_HALVES (128 * SSTH)
#define GEMM_SMEM (NSTG * 2 * STG_HALVES * 2)   // 81920 B

__device__ __forceinline__ void gemm_mainloop_f16(
    const __half* __restrict__ A, const __half* __restrict__ Bt,
    int K, int bm, int bn, float acc[4][4][4], __half* sm)
{
    const int tid  = threadIdx.x;
    const int lane = tid & 31;
    const int wid  = tid >> 5;
    const int wm   = (wid >> 2) * 64;
    const int wn   = (wid & 3) * 32;

    __half* As = sm;
    __half* Bs = sm + NSTG * STG_HALVES;
    const uint32_t as0 = smem_u32(As);
    const uint32_t bs0 = smem_u32(Bs);
    const int r0 = tid >> 1;               // row 0..127
    const int c0 = (tid & 1) * 16;         // half offset

    const uint32_t a_lane = (uint32_t)((((lane >> 3) & 1) * 8 + (lane & 7)) * (SSTH * 2)
                                       + (lane >> 4) * 16);
    const uint32_t b_lane4 = (uint32_t)((lane & 7) * (SSTH * 2)
                                        + ((lane >> 3) & 1) * 16
                                        + (lane >> 4) * 8 * (SSTH * 2));

    auto issue = [&](int ch) {
        const int s  = ch & (NSTG - 1);
        const int k0 = ch << 5;            // halves
        const uint32_t ao = as0 + (uint32_t)(s * STG_HALVES + r0 * SSTH + c0) * 2;
        const uint32_t bo = bs0 + (uint32_t)(s * STG_HALVES + r0 * SSTH + c0) * 2;
        cp16(ao,      A  + (size_t)(bm + r0) * K + k0 + c0);
        cp16(ao + 16, A  + (size_t)(bm + r0) * K + k0 + c0 + 8);
        cp16(bo,      Bt + (size_t)(bn + r0) * K + k0 + c0);
        cp16(bo + 16, Bt + (size_t)(bn + r0) * K + k0 + c0 + 8);
        CP_COMMIT();
    };

    const int niter = K >> 5;              // BK = 32 halves
    issue(0); issue(1); issue(2);

    for (int it = 0; it < niter; it++) {
        CP_WAIT2();
        __syncthreads();
        if (it + 3 < niter) issue(it + 3);

        const uint32_t abase = as0 + (uint32_t)((it & (NSTG - 1)) * STG_HALVES) * 2;
        const uint32_t bbase = bs0 + (uint32_t)((it & (NSTG - 1)) * STG_HALVES) * 2;

#pragma unroll
        for (int ks = 0; ks < 2; ks++) {   // two k16 steps, +32B each
            uint32_t afr[4][4], bfr[4][2];
#pragma unroll
            for (int mt = 0; mt < 4; mt++) {
                const uint32_t ad = abase
                    + (uint32_t)((wm + mt * 16) * (SSTH * 2)) + ks * 32 + a_lane;
                ldsm_x4(afr[mt][0], afr[mt][1], afr[mt][2], afr[mt][3], ad);
            }
#pragma unroll
            for (int nt = 0; nt < 4; nt += 2) {
                const uint32_t bd = bbase
                    + (uint32_t)((wn + nt * 8) * (SSTH * 2)) + ks * 32 + b_lane4;
                ldsm_x4(bfr[nt][0], bfr[nt][1], bfr[nt + 1][0], bfr[nt + 1][1], bd);
            }
#pragma unroll
            for (int mt = 0; mt < 4; mt++)
#pragma unroll
                for (int nt = 0; nt < 4; nt++)
                    mma_f16(acc[mt][nt], afr[mt][0], afr[mt][1], afr[mt][2],
                            afr[mt][3], bfr[nt][0], bfr[nt][1]);
        }
    }
}

// ---------------------------------------------------------------------------
// QKV GEMM (fp16) with fused RoPE + per-head pack epilogue (fp16 outputs).
// ---------------------------------------------------------------------------
__global__ __launch_bounds__(256, 2) void gemm_qkv_fused(
    const __half* __restrict__ A, const __half* __restrict__ Bt, int K)
{
    extern __shared__ __half smh[];
    const int tid  = threadIdx.x;
    const int lane = tid & 31;
    const int wid  = tid >> 5;
    const int wm   = (wid >> 2) * 64;
    const int wn   = (wid & 3) * 32;
    const int bm   = blockIdx.y * 128;
    const int bn   = blockIdx.x * 128;
    const int gid  = lane >> 2;
    const int tig  = lane & 3;

    float acc[4][4][4];
#pragma unroll
    for (int i = 0; i < 4; i++)
#pragma unroll
        for (int j = 0; j < 4; j++)
#pragma unroll
            for (int q = 0; q < 4; q++) acc[i][j][q] = 0.0f;

    gemm_mainloop_f16(A, Bt, K, bm, bn, acc, smh);

#pragma unroll
    for (int mt = 0; mt < 4; mt++) {
        const int rb = bm + wm + mt * 16 + gid;
#pragma unroll
        for (int nt = 0; nt < 4; nt++) {
            const int c  = bn + wn + nt * 8 + 2 * tig;
            const int region = c >> 10;
            const int cc = c & 1023;
            const int h  = cc >> 6;
            const int d  = cc & 63;
            const int i2 = d >> 1;
#pragma unroll
            for (int half = 0; half < 2; half++) {
                const int r = rb + half * 8;
                const int t = r & (T_SEQ - 1);
                const int b = r >> 11;
                const float a0 = acc[mt][nt][2 * half + 0];
                const float a1 = acc[mt][nt][2 * half + 1];
                const size_t dst =
                    ((size_t)(b * NHEAD + h) * T_SEQ + t) * HDIM + d;
                if (region == 2) {
                    *(__half2*)&g_vpk[dst] = __floats2half2_rn(a0, a1);
                } else {
                    const float sn = g_rope_tab[2 * (t * 32 + i2) + 0];
                    const float cs = g_rope_tab[2 * (t * 32 + i2) + 1];
                    float o0 = a0 * cs - a1 * sn;
                    float o1 = a1 * cs + a0 * sn;
                    if (region == 0) {
                        *(__half2*)&g_qpk[dst] =
                            __floats2half2_rn(o0 * 0.125f, o1 * 0.125f);
                    } else {
                        *(__half2*)&g_kpk[dst] = __floats2half2_rn(o0, o1);
                    }
                }
            }
        }
    }
}

// ---------------------------------------------------------------------------
// Plain fp16 GEMM, fp32 output (output projection)
// ---------------------------------------------------------------------------
__global__ __launch_bounds__(256, 2) void gemm_f16(
    const __half* __restrict__ A, const __half* __restrict__ Bt,
    float* __restrict__ C, int N, int K)
{
    extern __shared__ __half smh[];
    const int tid  = threadIdx.x;
    const int lane = tid & 31;
    const int wid  = tid >> 5;
    const int wm   = (wid >> 2) * 64;
    const int wn   = (wid & 3) * 32;
    const int bm   = blockIdx.y * 128;
    const int bn   = blockIdx.x * 128;
    const int gid  = lane >> 2;
    const int tig  = lane & 3;

    float acc[4][4][4];
#pragma unroll
    for (int i = 0; i < 4; i++)
#pragma unroll
        for (int j = 0; j < 4; j++)
#pragma unroll
            for (int q = 0; q < 4; q++) acc[i][j][q] = 0.0f;

    gemm_mainloop_f16(A, Bt, K, bm, bn, acc, smh);

#pragma unroll
    for (int mt = 0; mt < 4; mt++) {
        const int rb = bm + wm + mt * 16;
#pragma unroll
        for (int nt = 0; nt < 4; nt++) {
            const int cb = bn + wn + nt * 8 + 2 * tig;
            float2 lo = {acc[mt][nt][0], acc[mt][nt][1]};
            float2 hi = {acc[mt][nt][2], acc[mt][nt][3]};
            *(float2*)(C + (size_t)(rb + gid)     * N + cb) = lo;
            *(float2*)(C + (size_t)(rb + gid + 8) * N + cb) = hi;
        }
    }
}

// ===========================================================================
// fp16 tensor-core causal flash attention (128 q-rows, 8 warps).
// NO reg cap (R16 post-mortem: cap caused spill). Single __syncthreads per
// KV tile: the top barrier both publishes stage st and proves stage st^1
// was fully consumed in iteration kt-1, so next-tile issue follows it.
// ===========================================================================
#define SKP 72
#define SV  72
#define FA_SMEM ((2 * 64 * SKP + 2 * 64 * SV + 128 * SKP) * 2)   // 55296 B

__global__ __launch_bounds__(256) void flash_attn_tc()
{
    extern __shared__ __half smh[];
    __half* Ksm = smh;                       // [2][key][d]  stride 72
    __half* Vsm = Ksm + 2 * 64 * SKP;        // [2][key][d]  stride 72
    __half* Psm = Vsm + 2 * 64 * SV;         // [m][key]     stride 72

    const int tid  = threadIdx.x;
    const int lane = tid & 31;
    const int wid  = tid >> 5;
    const int gid  = lane >> 2;
    const int tig  = lane & 3;
    const int qi = (int)(gridDim.x - 1 - blockIdx.x);
    const int h = blockIdx.y, b = blockIdx.z;
    const int qbase = qi * 128;
    const int bh = b * NHEAD + h;
    const int wrow = 16 * wid;

    const uint32_t ksm0 = smem_u32(Ksm);
    const uint32_t vsm0 = smem_u32(Vsm);
    const uint32_t psm0 = smem_u32(Psm);
    const __half* kbase_p = g_kpk + (size_t)bh * T_SEQ * HDIM;
    const __half* vbase_p = g_vpk + (size_t)bh * T_SEQ * HDIM;

    const uint32_t k_lane4 = (uint32_t)((lane & 7) * (SKP * 2)
                                        + ((lane >> 3) & 1) * 16
                                        + (lane >> 4) * 8 * (SKP * 2));
    const uint32_t p_lane = (uint32_t)((((lane >> 3) & 1) * 8 + (lane & 7)) * (SKP * 2)
                                       + (lane >> 4) * 16);
    const uint32_t v_lane4 = (uint32_t)((lane & 15) * (SV * 2)
                                        + (lane >> 4) * 16);

    auto issue_kv = [&](int kt, int st) {
        const int n = tid >> 2;                 // key 0..63
        const int q = (tid & 3) * 16;           // half offset (32B chunks)
        const size_t go = (size_t)(kt * 64 + n) * HDIM + q;
        const uint32_t ko = (uint32_t)(st * 64 * SKP + n * SKP + q) * 2;
        const uint32_t vo = (uint32_t)(st * 64 * SV  + n * SV  + q) * 2;
        cp16(ko + ksm0,      kbase_p + go);
        cp16(ko + ksm0 + 16, kbase_p + go + 8);
        cp16(vo + vsm0,      vbase_p + go);
        cp16(vo + vsm0 + 16, vbase_p + go + 8);
    };

    // stage Q (fp16, pre-scaled) into Psm: 256 threads cover 128 rows
    {
        int m = tid >> 1;
        int d0 = (tid & 1) * 32;
        const __half* src = g_qpk + ((size_t)bh * T_SEQ + qbase + m) * HDIM + d0;
#pragma unroll
        for (int j = 0; j < 4; j++) {
            uint4 v = *(const uint4*)(src + 8 * j);
            *(uint4*)&Psm[m * SKP + d0 + 8 * j] = v;
        }
    }

    const int nkt = qbase / 64 + 2;
    issue_kv(0, 0);
    CP_COMMIT();
    __syncthreads();   // Q staged

    // hoist Q fragments (4 k16-steps over d=64)
    uint32_t qf[4][4];
#pragma unroll
    for (int kp = 0; kp < 4; kp++) {
        const uint32_t qa = psm0 + (uint32_t)(wrow * (SKP * 2)) + kp * 32 + p_lane;
        ldsm_x4(qf[kp][0], qf[kp][1], qf[kp][2], qf[kp][3], qa);
    }

    float Oacc[8][4];
#pragma unroll
    for (int nt = 0; nt < 8; nt++)
#pragma unroll
        for (int q = 0; q < 4; q++) Oacc[nt][q] = 0.0f;
    float mrow0 = -1e30f, mrow1 = -1e30f, lrow0 = 0.0f, lrow1 = 0.0f;

    for (int kt = 0; kt < nkt; kt++) {
        const int st = kt & 1;
        const int kb = kt * 64;
        const bool more = (kt + 1) < nkt;

        CP_WAIT0();        // this tile's K/V landed
        __syncthreads();   // publish stage st; proves st^1 fully consumed
        if (more) { issue_kv(kt + 1, st ^ 1); CP_COMMIT(); }

        const uint32_t kst = ksm0 + (uint32_t)(st * 64 * SKP * 2);
        const uint32_t vst = vsm0 + (uint32_t)(st * 64 * SV * 2);

        // ---- S = Q @ K^T  (K frags x4, nt-pairs) ----
        float sacc[8][4];
#pragma unroll
        for (int nt = 0; nt < 8; nt++)
#pragma unroll
            for (int q = 0; q < 4; q++) sacc[nt][q] = 0.0f;

#pragma unroll
        for (int kp = 0; kp < 4; kp++) {
#pragma unroll
            for (int nt = 0; nt < 8; nt += 2) {
                uint32_t b0, b1, b2, b3;
                const uint32_t ka = kst
                    + (uint32_t)(nt * 8 * (SKP * 2)) + kp * 32 + k_lane4;
                ldsm_x4(b0, b1, b2, b3, ka);
                mma_f16(sacc[nt],     qf[kp][0], qf[kp][1], qf[kp][2], qf[kp][3],
                        b0, b1);
                mma_f16(sacc[nt + 1], qf[kp][0], qf[kp][1], qf[kp][2], qf[kp][3],
                        b2, b3);
            }
        }

        // ---- causal mask (last two tiles only) ----
        const int r0g = qbase + wrow + gid;
        if (kb + 63 > qbase) {
#pragma unroll
            for (int nt = 0; nt < 8; nt++) {
                int col = kb + nt * 8 + 2 * tig;
                if (col     > r0g)     sacc[nt][0] = -1e30f;
                if (col + 1 > r0g)     sacc[nt][1] = -1e30f;
                if (col     > r0g + 8) sacc[nt][2] = -1e30f;
                if (col + 1 > r0g + 8) sacc[nt][3] = -1e30f;
            }
        }

        // ---- online softmax ----
        float mx0 = -1e30f, mx1 = -1e30f;
#pragma unroll
        for (int nt = 0; nt < 8; nt++) {
            mx0 = fmaxf(mx0, fmaxf(sacc[nt][0], sacc[nt][1]));
            mx1 = fmaxf(mx1, fmaxf(sacc[nt][2], sacc[nt][3]));
        }
        mx0 = fmaxf(mx0, __shfl_xor_sync(0xffffffffu, mx0, 1));
        mx0 = fmaxf(mx0, __shfl_xor_sync(0xffffffffu, mx0, 2));
        mx1 = fmaxf(mx1, __shfl_xor_sync(0xffffffffu, mx1, 1));
        mx1 = fmaxf(mx1, __shfl_xor_sync(0xffffffffu, mx1, 2));
        const float nm0 = fmaxf(mrow0, mx0);
        const float nm1 = fmaxf(mrow1, mx1);

        float sum0 = 0.0f, sum1 = 0.0f;
#pragma unroll
        for (int nt = 0; nt < 8; nt++) {
            float p00 = __expf(sacc[nt][0] - nm0);
            float p01 = __expf(sacc[nt][1] - nm0);
            float p10 = __expf(sacc[nt][2] - nm1);
            float p11 = __expf(sacc[nt][3] - nm1);
            sum0 += p00 + p01;
            sum1 += p10 + p11;
            *(__half2*)&Psm[(wrow + gid)     * SKP + nt * 8 + 2 * tig] =
                __floats2half2_rn(p00, p01);
            *(__half2*)&Psm[(wrow + gid + 8) * SKP + nt * 8 + 2 * tig] =
                __floats2half2_rn(p10, p11);
        }
        sum0 += __shfl_xor_sync(0xffffffffu, sum0, 1);
        sum0 += __shfl_xor_sync(0xffffffffu, sum0, 2);
        sum1 += __shfl_xor_sync(0xffffffffu, sum1, 1);
        sum1 += __shfl_xor_sync(0xffffffffu, sum1, 2);

        const float a0 = __expf(mrow0 - nm0);
        const float a1 = __expf(mrow1 - nm1);
        lrow0 = lrow0 * a0 + sum0;
        lrow1 = lrow1 * a1 + sum1;
        mrow0 = nm0; mrow1 = nm1;
#pragma unroll
        for (int nt = 0; nt < 8; nt++) {
            Oacc[nt][0] *= a0; Oacc[nt][1] *= a0;
            Oacc[nt][2] *= a1; Oacc[nt][3] *= a1;
        }
        __syncwarp();

        // ---- O += P @ V  (V frags x4.trans, nt-pairs) ----
#pragma unroll
        for (int kk = 0; kk < 4; kk++) {
            uint32_t a0f, a1f, a2f, a3f;
            const uint32_t pa = psm0
                + (uint32_t)(wrow * (SKP * 2)) + kk * 32 + p_lane;
            ldsm_x4(a0f, a1f, a2f, a3f, pa);
#pragma unroll
            for (int nt = 0; nt < 8; nt += 2) {
                uint32_t b0, b1, b2, b3;
                const uint32_t va = vst
                    + (uint32_t)(kk * 16 * (SV * 2)) + nt * 16 + v_lane4;
                ldsm_x4_trans(b0, b1, b2, b3, va);
                mma_f16(Oacc[nt],     a0f, a1f, a2f, a3f, b0, b1);
                mma_f16(Oacc[nt + 1], a0f, a1f, a2f, a3f, b2, b3);
            }
        }
    }

    const float i0 = 1.0f / lrow0;
    const float i1 = 1.0f / lrow1;
    const int r0g = qbase + wrow + gid;
#pragma unroll
    for (int nt = 0; nt < 8; nt++) {
        const int c = h * HDIM + nt * 8 + 2 * tig;
        *(__half2*)&g_attn16[((size_t)b * T_SEQ + r0g)     * DM + c] =
            __floats2half2_rn(Oacc[nt][0] * i0, Oacc[nt][1] * i0);
        *(__half2*)&g_attn16[((size_t)b * T_SEQ + r0g + 8) * DM + c] =
            __floats2half2_rn(Oacc[nt][2] * i1, Oacc[nt][3] * i1);
    }
}

// ===========================================================================
extern "C" void kernel_launch(void* const* d_in, const int* in_sizes, int n_in,
                              void* d_out, int out_size)
{
    const float* x    = (const float*)d_in[0];
    const float* Wqkv = (const float*)d_in[1];
    const float* Wout = (const float*)d_in[2];
    float* out = (float*)d_out;

    __half *attn16 = nullptr, *wqkvT = nullptr, *woutT = nullptr, *x16 = nullptr;
    cudaGetSymbolAddress((void**)&attn16, g_attn16);
    cudaGetSymbolAddress((void**)&wqkvT,  g_WqkvT16);
    cudaGetSymbolAddress((void**)&woutT,  g_WoutT16);
    cudaGetSymbolAddress((void**)&x16,    g_x16);

    cudaFuncSetAttribute(gemm_qkv_fused,
                         cudaFuncAttributeMaxDynamicSharedMemorySize, GEMM_SMEM);
    cudaFuncSetAttribute(gemm_f16,
                         cudaFuncAttributeMaxDynamicSharedMemorySize, GEMM_SMEM);
    cudaFuncSetAttribute(flash_attn_tc,
                         cudaFuncAttributeMaxDynamicSharedMemorySize, FA_SMEM);

    // 0) Fused prologue (x convert + both transposes + RoPE table)
    prologue_kernel<<<NB_TOTAL, 256>>>(x, Wqkv, Wout);

    // 1) QKV projection (fp16 mma) + fused RoPE + per-head pack
    gemm_qkv_fused<<<dim3(QKV_COLS / 128, ROWS / 128), 256, GEMM_SMEM>>>(
        x16, wqkvT, DM);

    // 2) Causal flash attention (fp16 mma, 128-row CTAs)
    flash_attn_tc<<<dim3(T_SEQ / 128, NHEAD, B_BATCH), 256, FA_SMEM>>>();

    // 3) Output projection (fp16 mma, fp32 out)
    gemm_f16<<<dim3(DM / 128, ROWS / 128), 256, GEMM_SMEM>>>(
        attn16, woutT, out, DM, DM);
}